// round 13
// baseline (speedup 1.0000x reference)
#include <cuda_runtime.h>
#include <cuda_bf16.h>
#include <mma.h>
#include <cstdint>
#include <cstddef>
#include <math.h>

using namespace nvcuda;

#define NNODE 650
#define NPAD  672              // K for A@h, multiple of 32
#define MP    704              // M padded to 11 tiles of 64
#define FDIM  512
#define NE    150000
#define ET    150650
#define NJT   8                // n-tiles (512/64)

// ---------------- device scratch ----------------
__device__ float g_x[NNODE * FDIM];                    // fp32 layer output (fc input)
__device__ int   g_C[NPAD * NPAD];                     // edge counts [dst][src]
__device__ float g_alsp[NJT * MP];                     // partial src logits
__device__ float g_aldp[NJT * MP];                     // partial dst logits
__device__ float g_sum[NNODE];

// bf16 split operands (row-major, padded; pad rows zeroed once per launch)
__device__ __nv_bfloat16 g_xh[MP * FDIM],   g_xl[MP * FDIM];     // X   [m][k], rows>=650 zero
__device__ __nv_bfloat16 g_wh[FDIM * FDIM], g_wl[FDIM * FDIM];   // W   [k][n]
__device__ __nv_bfloat16 g_hh[NPAD * FDIM], g_hl[NPAD * FDIM];   // h   [k][n], rows>=650 zero
__device__ __nv_bfloat16 g_ah[MP * NPAD],   g_al[MP * NPAD];     // A   [m][k], rows>=650 zero

__device__ __forceinline__ float leaky02(float x) { return fmaxf(x, 0.2f * x); }
__device__ __forceinline__ void bsplit(float v, __nv_bfloat16& hi, __nv_bfloat16& lo) {
    hi = __float2bfloat16(v);
    lo = __float2bfloat16(v - __bfloat162float(hi));
}

// ---------------- small kernels ----------------
__global__ void zeroc_kernel() {
    int i = blockIdx.x * 256 + threadIdx.x;          // NPAD*NPAD/4 exact
    *(int4*)&g_C[i * 4] = make_int4(0, 0, 0, 0);
}
__global__ void count_kernel(const int* __restrict__ ei) {
    int i = blockIdx.x * 256 + threadIdx.x;
    if (i >= ET) return;
    int s, d;
    if (i < NE) { s = ei[i]; d = ei[NE + i]; }
    else        { s = i - NE; d = s; }
    atomicAdd(&g_C[d * NPAD + s], 1);
}
// zero pad rows: x rows [650,704), h rows [650,672), A rows [650,704)
#define PADX (54 * FDIM)
#define PADH (22 * FDIM)
#define PADA (54 * NPAD)
__global__ void pad_kernel() {
    int i = blockIdx.x * 256 + threadIdx.x;
    __nv_bfloat16 z = __float2bfloat16(0.f);
    if (i < PADX) {
        g_xh[NNODE * FDIM + i] = z; g_xl[NNODE * FDIM + i] = z;
    } else if (i < PADX + PADH) {
        int j = i - PADX;
        g_hh[NNODE * FDIM + j] = z; g_hl[NNODE * FDIM + j] = z;
    } else if (i < PADX + PADH + PADA) {
        int j = i - PADX - PADH;
        g_ah[NNODE * NPAD + j] = z; g_al[NNODE * NPAD + j] = z;
    }
}
__global__ void conv_x0_kernel(const float* __restrict__ xs, const float* __restrict__ xt) {
    int i = blockIdx.x * 256 + threadIdx.x;
    if (i >= NNODE * FDIM) return;
    float v = (i < 400 * FDIM) ? xs[i] : xt[i - 400 * FDIM];
    __nv_bfloat16 hi, lo; bsplit(v, hi, lo);
    g_xh[i] = hi; g_xl[i] = lo;
}
__global__ void conv_w_kernel(const float* __restrict__ W) {
    int i = blockIdx.x * 256 + threadIdx.x;
    if (i >= FDIM * FDIM) return;
    __nv_bfloat16 hi, lo; bsplit(W[i], hi, lo);
    g_wh[i] = hi; g_wl[i] = lo;
}

// ---------------- build: logits -> A (bf16 split) + row sums ----------------
__global__ __launch_bounds__(256) void build_kernel() {
    const int d = blockIdx.x, t = threadIdx.x;
    __shared__ float s_als[NPAD];
    __shared__ float red[256];
    __shared__ float s_ald;

    for (int s = t; s < NPAD; s += 256) {
        float v = 0.f;
        if (s < NNODE) {
#pragma unroll
            for (int j = 0; j < NJT; j++) v += g_alsp[j * MP + s];
        }
        s_als[s] = v;
    }
    if (t == 0) {
        float v = 0.f;
#pragma unroll
        for (int j = 0; j < NJT; j++) v += g_aldp[j * MP + d];
        s_ald = v;
    }
    __syncthreads();

    float m = -1e30f;
    for (int s = t; s < NNODE; s += 256) m = fmaxf(m, s_als[s]);
    red[t] = m; __syncthreads();
    for (int o = 128; o > 0; o >>= 1) { if (t < o) red[t] = fmaxf(red[t], red[t + o]); __syncthreads(); }
    const float M = red[0];
    const float ald = s_ald;
    const float mp = leaky02(M + ald);      // valid softmax shift (>= segment max)
    __syncthreads();

    float lsum = 0.f;
    for (int s = t; s < NPAD; s += 256) {
        float p = 0.f;
        if (s < NNODE) {
            int c = g_C[d * NPAD + s];
            if (c) p = (float)c * expf(leaky02(s_als[s] + ald) - mp);
        }
        __nv_bfloat16 hi, lo; bsplit(p, hi, lo);
        g_ah[d * NPAD + s] = hi;
        g_al[d * NPAD + s] = lo;
        lsum += p;
    }
    red[t] = lsum; __syncthreads();
    for (int o = 128; o > 0; o >>= 1) { if (t < o) red[t] += red[t + o]; __syncthreads(); }
    if (t == 0) g_sum[d] = red[0];
}

// ---------------- wmma bf16-split GEMM ----------------
// mode 0: D = X @ W  (K=512) -> h bf16 hi/lo + logit partials (v1=a_src, v2=a_dst)
// mode 1: D = A @ h  (K=672) -> inv_sum + bias(v1) + act -> g_x fp32 + x bf16 hi/lo
// grid (8 n-tiles, 11 m-tiles), 128 threads = 2x2 warps, 64x64 block tile
__global__ __launch_bounds__(128) void mma_gemm_kernel(int mode,
                                                       const float* __restrict__ v1,
                                                       const float* __restrict__ v2,
                                                       int act) {
    __shared__ __align__(16) __nv_bfloat16 sAh[64 * 32], sAl[64 * 32];
    __shared__ __align__(16) __nv_bfloat16 sBh[32 * 72], sBl[32 * 72];
    __shared__ __align__(16) float sC[64 * 68];
    __shared__ float sV1[64], sV2[64];

    const int tid = threadIdx.x;
    const int wid = tid >> 5;
    const int bn = blockIdx.x * 64;
    const int m0 = blockIdx.y * 64;
    const int wm = (wid & 1) * 32;       // warp row offset in tile
    const int wn = (wid >> 1) * 32;      // warp col offset in tile

    const __nv_bfloat16 *pAh, *pAl, *pBh, *pBl;
    int Astride, nstage;
    if (mode == 0) { pAh = g_xh; pAl = g_xl; pBh = g_wh; pBl = g_wl; Astride = FDIM; nstage = 16; }
    else           { pAh = g_ah; pAl = g_al; pBh = g_hh; pBl = g_hl; Astride = NPAD; nstage = 21; }

    if (tid < 64)  sV1[tid] = v1[bn + tid];
    else           sV2[tid - 64] = v2[bn + tid - 64];

    wmma::fragment<wmma::accumulator, 16, 16, 16, float> acc[2][2];
#pragma unroll
    for (int i = 0; i < 2; i++)
#pragma unroll
        for (int j = 0; j < 2; j++)
            wmma::fill_fragment(acc[i][j], 0.f);

    for (int st = 0; st < nstage; st++) {
        const int k0 = st * 32;
        // load A tile 64x32 (hi+lo): 256 uint4 per array, 2 per thread
#pragma unroll
        for (int q = 0; q < 2; q++) {
            int idx = tid + q * 128;
            int row = idx >> 2, c8 = (idx & 3) * 8;
            size_t go = (size_t)(m0 + row) * Astride + k0 + c8;
            *(uint4*)&sAh[row * 32 + c8] = *(const uint4*)(pAh + go);
            *(uint4*)&sAl[row * 32 + c8] = *(const uint4*)(pAl + go);
        }
        // load B tile 32x64 (hi+lo)
#pragma unroll
        for (int q = 0; q < 2; q++) {
            int idx = tid + q * 128;
            int row = idx >> 3, c8 = (idx & 7) * 8;
            size_t go = (size_t)(k0 + row) * FDIM + bn + c8;
            *(uint4*)&sBh[row * 72 + c8] = *(const uint4*)(pBh + go);
            *(uint4*)&sBl[row * 72 + c8] = *(const uint4*)(pBl + go);
        }
        __syncthreads();

#pragma unroll
        for (int kk = 0; kk < 32; kk += 16) {
            wmma::fragment<wmma::matrix_a, 16, 16, 16, __nv_bfloat16, wmma::row_major> ah[2], al[2];
            wmma::fragment<wmma::matrix_b, 16, 16, 16, __nv_bfloat16, wmma::row_major> bh[2], bl[2];
#pragma unroll
            for (int i = 0; i < 2; i++) {
                wmma::load_matrix_sync(ah[i], &sAh[(wm + i * 16) * 32 + kk], 32);
                wmma::load_matrix_sync(al[i], &sAl[(wm + i * 16) * 32 + kk], 32);
            }
#pragma unroll
            for (int j = 0; j < 2; j++) {
                wmma::load_matrix_sync(bh[j], &sBh[kk * 72 + wn + j * 16], 72);
                wmma::load_matrix_sync(bl[j], &sBl[kk * 72 + wn + j * 16], 72);
            }
#pragma unroll
            for (int i = 0; i < 2; i++)
#pragma unroll
                for (int j = 0; j < 2; j++) {
                    wmma::mma_sync(acc[i][j], ah[i], bh[j], acc[i][j]);
                    wmma::mma_sync(acc[i][j], ah[i], bl[j], acc[i][j]);
                    wmma::mma_sync(acc[i][j], al[i], bh[j], acc[i][j]);
                }
        }
        __syncthreads();
    }

    // dump accumulators to smem C tile
#pragma unroll
    for (int i = 0; i < 2; i++)
#pragma unroll
        for (int j = 0; j < 2; j++)
            wmma::store_matrix_sync(&sC[(wm + i * 16) * 68 + wn + j * 16],
                                    acc[i][j], 68, wmma::mem_row_major);
    __syncthreads();

    if (mode == 0) {
        // write h (bf16 hi/lo) rows < 650
        for (int idx = tid; idx < 1024; idx += 128) {
            int row = idx >> 4, col = (idx & 15) * 4;
            int grow = m0 + row;
            if (grow >= NNODE) continue;
            float4 v = *(const float4*)&sC[row * 68 + col];
            __nv_bfloat16 h0,l0,h1,l1,h2,l2,h3,l3;
            bsplit(v.x,h0,l0); bsplit(v.y,h1,l1); bsplit(v.z,h2,l2); bsplit(v.w,h3,l3);
            size_t go = (size_t)grow * FDIM + bn + col;
            ((__nv_bfloat162*)(g_hh + go))[0] = __nv_bfloat162(h0, h1);
            ((__nv_bfloat162*)(g_hh + go))[1] = __nv_bfloat162(h2, h3);
            ((__nv_bfloat162*)(g_hl + go))[0] = __nv_bfloat162(l0, l1);
            ((__nv_bfloat162*)(g_hl + go))[1] = __nv_bfloat162(l2, l3);
        }
        // partial logits: threads 0..63 -> sa, 64..127 -> sd
        int r = tid & 63;
        int grow = m0 + r;
        const float* vv = (tid < 64) ? sV1 : sV2;
        float s = 0.f;
#pragma unroll 8
        for (int c = 0; c < 64; c++) s += sC[r * 68 + c] * vv[c];
        if (grow < NNODE) {
            if (tid < 64) g_alsp[blockIdx.x * MP + grow] = s;
            else          g_aldp[blockIdx.x * MP + grow] = s;
        }
    } else {
        for (int idx = tid; idx < 1024; idx += 128) {
            int row = idx >> 4, col = (idx & 15) * 4;
            int grow = m0 + row;
            if (grow >= NNODE) continue;
            float inv = 1.f / (g_sum[grow] + 1e-16f);
            float4 v = *(const float4*)&sC[row * 68 + col];
            float o0 = v.x * inv + sV1[col + 0];
            float o1 = v.y * inv + sV1[col + 1];
            float o2 = v.z * inv + sV1[col + 2];
            float o3 = v.w * inv + sV1[col + 3];
            if (act) {
                o0 = o0 > 0.f ? o0 : 0.01f * o0; o1 = o1 > 0.f ? o1 : 0.01f * o1;
                o2 = o2 > 0.f ? o2 : 0.01f * o2; o3 = o3 > 0.f ? o3 : 0.01f * o3;
            } else {
                o0 = fmaxf(o0, 0.f); o1 = fmaxf(o1, 0.f);
                o2 = fmaxf(o2, 0.f); o3 = fmaxf(o3, 0.f);
            }
            size_t go = (size_t)grow * FDIM + bn + col;
            *(float4*)&g_x[go] = make_float4(o0, o1, o2, o3);
            __nv_bfloat16 h0,l0,h1,l1,h2,l2,h3,l3;
            bsplit(o0,h0,l0); bsplit(o1,h1,l1); bsplit(o2,h2,l2); bsplit(o3,h3,l3);
            ((__nv_bfloat162*)(g_xh + go))[0] = __nv_bfloat162(h0, h1);
            ((__nv_bfloat162*)(g_xh + go))[1] = __nv_bfloat162(h2, h3);
            ((__nv_bfloat162*)(g_xl + go))[0] = __nv_bfloat162(l0, l1);
            ((__nv_bfloat162*)(g_xl + go))[1] = __nv_bfloat162(l2, l3);
        }
    }
}

// ---------------- fc + sigmoid ----------------
__global__ __launch_bounds__(256) void fc_kernel(const float* __restrict__ fcw,
                                                 const float* __restrict__ fcb,
                                                 float* __restrict__ out) {
    int j = blockIdx.x;
    int t = threadIdx.x;
    float acc = 0.f;
    const float* y = &g_x[j * NNODE];     // flat .view: [512][650]
    for (int k = t; k < NNODE; k += 256) acc += y[k] * fcw[k];
    __shared__ float r[256];
    r[t] = acc; __syncthreads();
    for (int s = 128; s > 0; s >>= 1) { if (t < s) r[t] += r[t + s]; __syncthreads(); }
    if (t == 0) out[j] = 1.f / (1.f + expf(-(r[0] + fcb[0])));
}

// ---------------- launch ----------------
extern "C" void kernel_launch(void* const* d_in, const int* in_sizes, int n_in,
                              void* d_out, int out_size) {
    const float* x_s = (const float*)d_in[0];
    const float* x_t = (const float*)d_in[1];
    const int*   ei  = (const int*)  d_in[2];
    const float* W1  = (const float*)d_in[5];
    const float* as1 = (const float*)d_in[6];
    const float* ad1 = (const float*)d_in[7];
    const float* b1  = (const float*)d_in[8];
    const float* W4  = (const float*)d_in[9];
    const float* as4 = (const float*)d_in[10];
    const float* ad4 = (const float*)d_in[11];
    const float* b4  = (const float*)d_in[12];
    const float* fcw = (const float*)d_in[13];
    const float* fcb = (const float*)d_in[14];
    float* out = (float*)d_out;

    dim3 mgrid(NJT, MP / 64);                      // 8 x 11

    zeroc_kernel<<<NPAD * NPAD / 4 / 256, 256>>>();
    count_kernel<<<(ET + 255) / 256, 256>>>(ei);
    pad_kernel<<<(PADX + PADH + PADA + 255) / 256, 256>>>();
    conv_x0_kernel<<<(NNODE * FDIM + 255) / 256, 256>>>(x_s, x_t);

    // layer 1
    conv_w_kernel<<<(FDIM * FDIM + 255) / 256, 256>>>(W1);
    mma_gemm_kernel<<<mgrid, 128>>>(0, as1, ad1, 0);
    build_kernel<<<NNODE, 256>>>();
    mma_gemm_kernel<<<mgrid, 128>>>(1, b1, b1, 0);     // relu

    // layer 2
    conv_w_kernel<<<(FDIM * FDIM + 255) / 256, 256>>>(W4);
    mma_gemm_kernel<<<mgrid, 128>>>(0, as4, ad4, 0);
    build_kernel<<<NNODE, 256>>>();
    mma_gemm_kernel<<<mgrid, 128>>>(1, b4, b4, 1);     // leaky 0.01

    fc_kernel<<<FDIM, 256>>>(fcw, fcb, out);
}

// round 17
// speedup vs baseline: 1.0955x; 1.0955x over previous
#include <cuda_runtime.h>
#include <cuda_bf16.h>
#include <mma.h>
#include <cstdint>
#include <cstddef>
#include <math.h>

using namespace nvcuda;

#define NNODE 650
#define NPAD  672              // K for A@h, multiple of 32
#define MP    704              // M padded to 11 tiles of 64
#define FDIM  512
#define NE    150000
#define ET    150650
#define NJT   8                // n-tiles (512/64)

// ---------------- device scratch (all fp32; bf16 split happens in-GEMM) ------
__device__ float g_x[NNODE * FDIM];       // layer output (fc input / layer-2 X)
__device__ float g_h[NNODE * FDIM];       // h = X @ W
__device__ float g_A[NNODE * NPAD];       // attention matrix [dst][src]
__device__ int   g_C[NPAD * NPAD];        // edge counts
__device__ float g_alsp[NJT * MP];        // partial src logits
__device__ float g_aldp[NJT * MP];        // partial dst logits
__device__ float g_sum[NNODE];

__device__ __forceinline__ float leaky02(float x) { return fmaxf(x, 0.2f * x); }

// split one float4 into bf16 hi/lo and store 4+4 at ph/pl (8B each)
__device__ __forceinline__ void split4(float4 v, __nv_bfloat16* ph, __nv_bfloat16* pl) {
    __nv_bfloat16 h0 = __float2bfloat16(v.x), h1 = __float2bfloat16(v.y);
    __nv_bfloat16 h2 = __float2bfloat16(v.z), h3 = __float2bfloat16(v.w);
    __nv_bfloat16 l0 = __float2bfloat16(v.x - __bfloat162float(h0));
    __nv_bfloat16 l1 = __float2bfloat16(v.y - __bfloat162float(h1));
    __nv_bfloat16 l2 = __float2bfloat16(v.z - __bfloat162float(h2));
    __nv_bfloat16 l3 = __float2bfloat16(v.w - __bfloat162float(h3));
    ((__nv_bfloat162*)ph)[0] = __nv_bfloat162(h0, h1);
    ((__nv_bfloat162*)ph)[1] = __nv_bfloat162(h2, h3);
    ((__nv_bfloat162*)pl)[0] = __nv_bfloat162(l0, l1);
    ((__nv_bfloat162*)pl)[1] = __nv_bfloat162(l2, l3);
}

// ---------------- small kernels ----------------
__global__ void zeroc_kernel() {
    int i = blockIdx.x * 256 + threadIdx.x;          // NPAD*NPAD/4 exact
    *(int4*)&g_C[i * 4] = make_int4(0, 0, 0, 0);
}
__global__ void count_kernel(const int* __restrict__ ei) {
    int i = blockIdx.x * 256 + threadIdx.x;
    if (i >= ET) return;
    int s, d;
    if (i < NE) { s = ei[i]; d = ei[NE + i]; }
    else        { s = i - NE; d = s; }
    atomicAdd(&g_C[d * NPAD + s], 1);
}

// ---------------- build: logits -> A fp32 + row sums ----------------
__global__ __launch_bounds__(256) void build_kernel() {
    const int d = blockIdx.x, t = threadIdx.x;
    __shared__ float s_als[NPAD];
    __shared__ float red[256];
    __shared__ float s_ald;

    for (int s = t; s < NPAD; s += 256) {
        float v = 0.f;
        if (s < NNODE) {
#pragma unroll
            for (int j = 0; j < NJT; j++) v += g_alsp[j * MP + s];
        }
        s_als[s] = v;
    }
    if (t == 0) {
        float v = 0.f;
#pragma unroll
        for (int j = 0; j < NJT; j++) v += g_aldp[j * MP + d];
        s_ald = v;
    }
    __syncthreads();

    float m = -1e30f;
    for (int s = t; s < NNODE; s += 256) m = fmaxf(m, s_als[s]);
    red[t] = m; __syncthreads();
    for (int o = 128; o > 0; o >>= 1) { if (t < o) red[t] = fmaxf(red[t], red[t + o]); __syncthreads(); }
    const float M = red[0];
    const float ald = s_ald;
    const float mp = leaky02(M + ald);      // valid softmax shift (>= segment max)
    __syncthreads();

    float lsum = 0.f;
    for (int s = t; s < NPAD; s += 256) {
        float p = 0.f;
        if (s < NNODE) {
            int c = g_C[d * NPAD + s];
            if (c) p = (float)c * __expf(leaky02(s_als[s] + ald) - mp);
        }
        g_A[d * NPAD + s] = p;
        lsum += p;
    }
    red[t] = lsum; __syncthreads();
    for (int o = 128; o > 0; o >>= 1) { if (t < o) red[t] += red[t + o]; __syncthreads(); }
    if (t == 0) g_sum[d] = red[0];
}

// ---------------- wmma bf16-split GEMM, double-buffered pipeline -------------
// mode 0: D = X @ W  (K=512, B=W fp32 param)  -> g_h fp32 + logit partials
//         use_gx=0: X = concat(xs,xt); use_gx=1: X = g_x
// mode 1: D = A @ h  (K=672, A=g_A, B=g_h)    -> inv_sum+bias(v1)+act -> g_x
// grid (8 n-tiles, 11 m-tiles), 128 threads = 2x2 warps, 64x64 tile
#define AHOFF 0
#define ALOFF 8192
#define BHOFF 16384
#define BLOFF 25600
// buffer strides: A 4096B, B 4608B; total pipeline 34816B; sC (17408B) aliases base

__global__ __launch_bounds__(128) void mma_gemm_kernel(int mode, int use_gx,
                                                       const float* __restrict__ xs,
                                                       const float* __restrict__ xt,
                                                       const float* __restrict__ W,
                                                       const float* __restrict__ v1,
                                                       const float* __restrict__ v2,
                                                       int act) {
    __shared__ __align__(16) char SM[34816];
    __shared__ float sV1[64], sV2[64];

    const int tid = threadIdx.x;
    const int wid = tid >> 5;
    const int bn = blockIdx.x * 64;
    const int m0 = blockIdx.y * 64;
    const int wm = (wid & 1) * 32;
    const int wn = (wid >> 1) * 32;

    const int nstage = mode ? 21 : 16;
    const int astride = mode ? NPAD : FDIM;

    // ---- A operand row pointer (pre-offset by this thread's column base) ----
    const int arow = tid >> 1, ac0 = (tid & 1) * 16;
    const int grA = m0 + arow;
    const float* aptr = nullptr;
    if (grA < NNODE) {
        if (mode)          aptr = g_A + (size_t)grA * NPAD;
        else if (use_gx)   aptr = g_x + (size_t)grA * FDIM;
        else if (grA < 400) aptr = xs + (size_t)grA * FDIM;
        else               aptr = xt + (size_t)(grA - 400) * FDIM;
    }
    if (aptr) aptr += ac0;

    // ---- B operand base (row brow, col bn+bc0) ----
    const int brow = tid >> 2, bc0 = (tid & 3) * 16;
    const float* bbase = (mode ? (const float*)g_h : W) + (size_t)brow * FDIM + bn + bc0;

    if (tid < 64)  sV1[tid] = v1[bn + tid];
    else           sV2[tid - 64] = v2[bn + tid - 64];

    wmma::fragment<wmma::accumulator, 16, 16, 16, float> acc[2][2];
#pragma unroll
    for (int i = 0; i < 2; i++)
#pragma unroll
        for (int j = 0; j < 2; j++)
            wmma::fill_fragment(acc[i][j], 0.f);

    float4 pa[4], pb[4];
    // prefetch stage 0
    {
        const int k0 = 0;
#pragma unroll
        for (int q = 0; q < 4; q++)
            pa[q] = aptr ? *(const float4*)(aptr + k0 + q * 4) : make_float4(0.f,0.f,0.f,0.f);
        bool bok = (mode == 0) || (k0 + brow < NNODE);
#pragma unroll
        for (int q = 0; q < 4; q++)
            pb[q] = bok ? *(const float4*)(bbase + (size_t)k0 * FDIM + q * 4) : make_float4(0.f,0.f,0.f,0.f);
    }

    for (int s = 0; s < nstage; s++) {
        const int buf = s & 1;
        __nv_bfloat16* ah = (__nv_bfloat16*)(SM + AHOFF + buf * 4096) + arow * 32 + ac0;
        __nv_bfloat16* al = (__nv_bfloat16*)(SM + ALOFF + buf * 4096) + arow * 32 + ac0;
        __nv_bfloat16* bh = (__nv_bfloat16*)(SM + BHOFF + buf * 4608) + brow * 72 + bc0;
        __nv_bfloat16* bl = (__nv_bfloat16*)(SM + BLOFF + buf * 4608) + brow * 72 + bc0;
#pragma unroll
        for (int q = 0; q < 4; q++) {
            split4(pa[q], ah + q * 4, al + q * 4);
            split4(pb[q], bh + q * 4, bl + q * 4);
        }
        __syncthreads();

        // prefetch next stage while computing this one
        if (s + 1 < nstage) {
            const int k0 = (s + 1) * 32;
#pragma unroll
            for (int q = 0; q < 4; q++)
                pa[q] = aptr ? *(const float4*)(aptr + k0 + q * 4) : make_float4(0.f,0.f,0.f,0.f);
            bool bok = (mode == 0) || (k0 + brow < NNODE);
#pragma unroll
            for (int q = 0; q < 4; q++)
                pb[q] = bok ? *(const float4*)(bbase + (size_t)k0 * FDIM + q * 4) : make_float4(0.f,0.f,0.f,0.f);
        }

        const __nv_bfloat16* pAH = (const __nv_bfloat16*)(SM + AHOFF + buf * 4096);
        const __nv_bfloat16* pAL = (const __nv_bfloat16*)(SM + ALOFF + buf * 4096);
        const __nv_bfloat16* pBH = (const __nv_bfloat16*)(SM + BHOFF + buf * 4608);
        const __nv_bfloat16* pBL = (const __nv_bfloat16*)(SM + BLOFF + buf * 4608);
#pragma unroll
        for (int kk = 0; kk < 32; kk += 16) {
            wmma::fragment<wmma::matrix_a, 16, 16, 16, __nv_bfloat16, wmma::row_major> fah[2], fal[2];
            wmma::fragment<wmma::matrix_b, 16, 16, 16, __nv_bfloat16, wmma::row_major> fbh[2], fbl[2];
#pragma unroll
            for (int i = 0; i < 2; i++) {
                wmma::load_matrix_sync(fah[i], pAH + (wm + i * 16) * 32 + kk, 32);
                wmma::load_matrix_sync(fal[i], pAL + (wm + i * 16) * 32 + kk, 32);
            }
#pragma unroll
            for (int j = 0; j < 2; j++) {
                wmma::load_matrix_sync(fbh[j], pBH + kk * 72 + wn + j * 16, 72);
                wmma::load_matrix_sync(fbl[j], pBL + kk * 72 + wn + j * 16, 72);
            }
            // product-major: same-acc chain distance = 4
#pragma unroll
            for (int i = 0; i < 2; i++)
#pragma unroll
                for (int j = 0; j < 2; j++)
                    wmma::mma_sync(acc[i][j], fah[i], fbh[j], acc[i][j]);
#pragma unroll
            for (int i = 0; i < 2; i++)
#pragma unroll
                for (int j = 0; j < 2; j++)
                    wmma::mma_sync(acc[i][j], fah[i], fbl[j], acc[i][j]);
#pragma unroll
            for (int i = 0; i < 2; i++)
#pragma unroll
                for (int j = 0; j < 2; j++)
                    wmma::mma_sync(acc[i][j], fal[i], fbh[j], acc[i][j]);
        }
        // NOTE: no trailing sync; next store targets the other buffer.
    }

    // ---- dump accumulators to C tile (aliases pipeline buffers) ----
    __syncthreads();
    float* sC = (float*)SM;
#pragma unroll
    for (int i = 0; i < 2; i++)
#pragma unroll
        for (int j = 0; j < 2; j++)
            wmma::store_matrix_sync(&sC[(wm + i * 16) * 68 + wn + j * 16],
                                    acc[i][j], 68, wmma::mem_row_major);
    __syncthreads();

    if (mode == 0) {
        for (int idx = tid; idx < 1024; idx += 128) {
            int row = idx >> 4, col = (idx & 15) * 4;
            int grow = m0 + row;
            if (grow >= NNODE) continue;
            *(float4*)&g_h[(size_t)grow * FDIM + bn + col] = *(const float4*)&sC[row * 68 + col];
        }
        int r = tid & 63;
        int grow = m0 + r;
        const float* vv = (tid < 64) ? sV1 : sV2;
        float s = 0.f;
#pragma unroll 8
        for (int c = 0; c < 64; c++) s += sC[r * 68 + c] * vv[c];
        if (grow < NNODE) {
            if (tid < 64) g_alsp[blockIdx.x * MP + grow] = s;
            else          g_aldp[blockIdx.x * MP + grow] = s;
        }
    } else {
        for (int idx = tid; idx < 1024; idx += 128) {
            int row = idx >> 4, col = (idx & 15) * 4;
            int grow = m0 + row;
            if (grow >= NNODE) continue;
            float inv = 1.f / (g_sum[grow] + 1e-16f);
            float4 v = *(const float4*)&sC[row * 68 + col];
            float o0 = v.x * inv + sV1[col + 0];
            float o1 = v.y * inv + sV1[col + 1];
            float o2 = v.z * inv + sV1[col + 2];
            float o3 = v.w * inv + sV1[col + 3];
            if (act) {
                o0 = o0 > 0.f ? o0 : 0.01f * o0; o1 = o1 > 0.f ? o1 : 0.01f * o1;
                o2 = o2 > 0.f ? o2 : 0.01f * o2; o3 = o3 > 0.f ? o3 : 0.01f * o3;
            } else {
                o0 = fmaxf(o0, 0.f); o1 = fmaxf(o1, 0.f);
                o2 = fmaxf(o2, 0.f); o3 = fmaxf(o3, 0.f);
            }
            *(float4*)&g_x[(size_t)grow * FDIM + bn + col] = make_float4(o0, o1, o2, o3);
        }
    }
}

// ---------------- fc + sigmoid ----------------
__global__ __launch_bounds__(256) void fc_kernel(const float* __restrict__ fcw,
                                                 const float* __restrict__ fcb,
                                                 float* __restrict__ out) {
    int j = blockIdx.x;
    int t = threadIdx.x;
    float acc = 0.f;
    const float* y = &g_x[j * NNODE];     // flat .view: [512][650]
    for (int k = t; k < NNODE; k += 256) acc += y[k] * fcw[k];
    __shared__ float r[256];
    r[t] = acc; __syncthreads();
    for (int s = 128; s > 0; s >>= 1) { if (t < s) r[t] += r[t + s]; __syncthreads(); }
    if (t == 0) out[j] = 1.f / (1.f + expf(-(r[0] + fcb[0])));
}

// ---------------- launch ----------------
extern "C" void kernel_launch(void* const* d_in, const int* in_sizes, int n_in,
                              void* d_out, int out_size) {
    const float* x_s = (const float*)d_in[0];
    const float* x_t = (const float*)d_in[1];
    const int*   ei  = (const int*)  d_in[2];
    const float* W1  = (const float*)d_in[5];
    const float* as1 = (const float*)d_in[6];
    const float* ad1 = (const float*)d_in[7];
    const float* b1  = (const float*)d_in[8];
    const float* W4  = (const float*)d_in[9];
    const float* as4 = (const float*)d_in[10];
    const float* ad4 = (const float*)d_in[11];
    const float* b4  = (const float*)d_in[12];
    const float* fcw = (const float*)d_in[13];
    const float* fcb = (const float*)d_in[14];
    float* out = (float*)d_out;

    dim3 mgrid(NJT, MP / 64);                      // 8 x 11 = 88 blocks

    zeroc_kernel<<<NPAD * NPAD / 4 / 256, 256>>>();
    count_kernel<<<(ET + 255) / 256, 256>>>(ei);

    // layer 1
    mma_gemm_kernel<<<mgrid, 128>>>(0, 0, x_s, x_t, W1, as1, ad1, 0);
    build_kernel<<<NNODE, 256>>>();
    mma_gemm_kernel<<<mgrid, 128>>>(1, 0, x_s, x_t, W1, b1, b1, 0);    // relu

    // layer 2
    mma_gemm_kernel<<<mgrid, 128>>>(0, 1, x_s, x_t, W4, as4, ad4, 0);
    build_kernel<<<NNODE, 256>>>();
    mma_gemm_kernel<<<mgrid, 128>>>(1, 0, x_s, x_t, W4, b4, b4, 1);    // leaky 0.01

    fc_kernel<<<FDIM, 256>>>(fcw, fcb, out);
}